// round 1
// baseline (speedup 1.0000x reference)
#include <cuda_runtime.h>
#include <math.h>

// Problem constants
#define NB 16
#define NC 64
#define NO 64
#define NH 160
#define NW 160
#define NK 8
#define NA 16
#define KHW 9
#define PLANE (NH*NW)          // 25600
#define CC 8                   // c-chunk in conv

// Scratch (device globals; no allocation allowed)
__device__ float g_gap [NB*NC];
__device__ float g_chan[NB*NC];
__device__ float g_filt[NB*NO];
__device__ float g_spat[NB*KHW];
__device__ float g_katt[NB*NK];
__device__ float g_W   [NB*NC*KHW*NO];   // [b][c][khw][o], gates folded in

// ---------------------------------------------------------------------------
// 1) Global average pool: one block per (b,c) plane
// ---------------------------------------------------------------------------
__global__ void gap_kernel(const float* __restrict__ x) {
    const int plane = blockIdx.x;                       // b*64 + c
    const float4* xp = (const float4*)(x + (size_t)plane * PLANE);
    float s = 0.f;
    for (int i = threadIdx.x; i < PLANE / 4; i += 256) {
        float4 v = xp[i];
        s += (v.x + v.y) + (v.z + v.w);
    }
    #pragma unroll
    for (int off = 16; off; off >>= 1) s += __shfl_down_sync(0xffffffffu, s, off);
    __shared__ float sm[8];
    if ((threadIdx.x & 31) == 0) sm[threadIdx.x >> 5] = s;
    __syncthreads();
    if (threadIdx.x == 0) {
        float t = 0.f;
        #pragma unroll
        for (int i = 0; i < 8; i++) t += sm[i];
        g_gap[plane] = t * (1.f / (float)PLANE);
    }
}

// ---------------------------------------------------------------------------
// 2) Routing MLP + BN + 4 attention heads: one block (128 thr) per batch b
// ---------------------------------------------------------------------------
__global__ void att_kernel(const float* __restrict__ scale,
                           const float* __restrict__ rw1, const float* __restrict__ rb1,
                           const float* __restrict__ rw2, const float* __restrict__ rb2,
                           const float* __restrict__ fc_w,
                           const float* __restrict__ bn_g, const float* __restrict__ bn_b,
                           const float* __restrict__ bn_m, const float* __restrict__ bn_v,
                           const float* __restrict__ cfc_w, const float* __restrict__ cfc_b,
                           const float* __restrict__ ffc_w, const float* __restrict__ ffc_b,
                           const float* __restrict__ sfc_w, const float* __restrict__ sfc_b,
                           const float* __restrict__ kfc_w, const float* __restrict__ kfc_b) {
    const int b = blockIdx.x;
    const int t = threadIdx.x;
    __shared__ float s[66], h1[128], rt[64], v[16], kl[8];

    if (t < 2)       s[t] = 1.f / scale[t];
    else if (t < 66) s[t] = g_gap[b * NC + (t - 2)];
    __syncthreads();

    {   // layer 1: [128,66]
        float a = rb1[t];
        #pragma unroll 6
        for (int i = 0; i < 66; i++) a += rw1[t * 66 + i] * s[i];
        h1[t] = fmaxf(a, 0.f);
    }
    __syncthreads();
    if (t < 64) {   // layer 2: [64,128]
        float a = rb2[t];
        #pragma unroll 8
        for (int i = 0; i < 128; i++) a += rw2[t * 128 + i] * h1[i];
        rt[t] = fmaxf(a, 0.f);
    }
    __syncthreads();
    if (t < NA) {   // trunk: fc (no bias) + BN(eval) + relu
        float a = 0.f;
        #pragma unroll 8
        for (int i = 0; i < 64; i++) a += fc_w[t * 64 + i] * rt[i];
        a = (a - bn_m[t]) * rsqrtf(bn_v[t] + 1e-5f) * bn_g[t] + bn_b[t];
        v[t] = fmaxf(a, 0.f);
    }
    __syncthreads();
    if (t < 64) {
        float a = cfc_b[t], f = ffc_b[t];
        #pragma unroll
        for (int i = 0; i < NA; i++) { a += cfc_w[t * NA + i] * v[i]; f += ffc_w[t * NA + i] * v[i]; }
        g_chan[b * NC + t] = 1.f / (1.f + expf(-a));
        g_filt[b * NO + t] = 1.f / (1.f + expf(-f));
    }
    if (t < KHW) {
        float a = sfc_b[t];
        #pragma unroll
        for (int i = 0; i < NA; i++) a += sfc_w[t * NA + i] * v[i];
        g_spat[b * KHW + t] = 1.f / (1.f + expf(-a));
    }
    if (t < NK) {
        float a = kfc_b[t];
        #pragma unroll
        for (int i = 0; i < NA; i++) a += kfc_w[t * NA + i] * v[i];
        kl[t] = a;
    }
    __syncthreads();
    if (t == 0) {   // softmax over 8 experts
        float m = kl[0];
        #pragma unroll
        for (int i = 1; i < NK; i++) m = fmaxf(m, kl[i]);
        float e[NK], sum = 0.f;
        #pragma unroll
        for (int i = 0; i < NK; i++) { e[i] = expf(kl[i] - m); sum += e[i]; }
        float inv = 1.f / sum;
        #pragma unroll
        for (int i = 0; i < NK; i++) g_katt[b * NK + i] = e[i] * inv;
    }
}

// ---------------------------------------------------------------------------
// 3) Per-sample aggregated weights with all gates folded in.
//    Block = (b, o); threads stride over e = c*9+khw (coalesced weight reads).
//    g_W layout: [b][c][khw][o]  (o contiguous -> conv reads via float4)
// ---------------------------------------------------------------------------
__global__ void wprep_kernel(const float* __restrict__ weight) {
    const int b = blockIdx.x >> 6;
    const int o = blockIdx.x & 63;
    __shared__ float ka[NK], sp[KHW], ch[NC], fo;
    const int t = threadIdx.x;
    if (t < NK)               ka[t]      = g_katt[b * NK + t];
    else if (t < NK + KHW)    sp[t - NK] = g_spat[b * KHW + (t - NK)];
    else if (t < NK + KHW + NC) ch[t - NK - KHW] = g_chan[b * NC + (t - NK - KHW)];
    else if (t == NK + KHW + NC) fo = g_filt[b * NO + o];
    __syncthreads();

    const float* wo = weight + (size_t)o * (NC * KHW);     // + k*NO*NC*KHW
    for (int e = t; e < NC * KHW; e += blockDim.x) {
        float a = 0.f;
        #pragma unroll
        for (int k = 0; k < NK; k++)
            a += ka[k] * wo[(size_t)k * NO * NC * KHW + e];
        const int c = e / KHW, khw = e - c * KHW;
        g_W[(((size_t)b * NC + c) * KHW + khw) * NO + o] = a * fo * ch[c] * sp[khw];
    }
}

// ---------------------------------------------------------------------------
// 4) Conv: block = (output row h, batch b). 64 o x 160 px per block.
//    threads (40,8): tx -> 4 contiguous cols, ty -> 8 output channels.
//    SMEM-chunked over c (CC=8). Register tile 8o x 4px = 32 FMAs per
//    (c,kh,kw) step per thread -> FFMA-issue bound, not LDS bound.
// ---------------------------------------------------------------------------
__global__ __launch_bounds__(320, 2)
void conv_kernel(const float* __restrict__ x, float* __restrict__ out) {
    const int h  = blockIdx.x;
    const int b  = blockIdx.y;
    const int tx = threadIdx.x;     // 0..39
    const int ty = threadIdx.y;     // 0..7
    const int tid = ty * 40 + tx;

    __shared__ __align__(16) float xs[CC][3][164];   // cols: input col = i-1 (zero pad)
    __shared__ __align__(16) float ws[CC][KHW][NO];

    float acc[8][4];
    #pragma unroll
    for (int i = 0; i < 8; i++)
        #pragma unroll
        for (int j = 0; j < 4; j++) acc[i][j] = 0.f;

    const float* xb = x   + (size_t)b * NC * PLANE;
    const float* wb = g_W + (size_t)b * NC * KHW * NO;

    for (int c0 = 0; c0 < NC; c0 += CC) {
        // --- load x chunk (rows h-1..h+1, cols -1..160 zero-padded) ---
        for (int e = tid; e < CC * 3 * 164; e += 320) {
            const int cc  = e / (3 * 164);
            const int rem = e - cc * (3 * 164);
            const int kh  = rem / 164;
            const int i   = rem - kh * 164;
            const int row = h - 1 + kh;
            const int col = i - 1;
            float val = 0.f;
            if (i < 162 && (unsigned)col < NW && (unsigned)row < NH)
                val = xb[(size_t)(c0 + cc) * PLANE + row * NW + col];
            xs[cc][kh][i] = val;
        }
        // --- load weight chunk (contiguous in g_W) ---
        for (int e = tid; e < CC * KHW * NO; e += 320)
            ((float*)ws)[e] = wb[(size_t)c0 * KHW * NO + e];
        __syncthreads();

        for (int cc = 0; cc < CC; cc++) {
            #pragma unroll
            for (int kh = 0; kh < 3; kh++) {
                float xv[6];
                const float4 x4 = *(const float4*)&xs[cc][kh][tx * 4];
                const float2 x2 = *(const float2*)&xs[cc][kh][tx * 4 + 4];
                xv[0] = x4.x; xv[1] = x4.y; xv[2] = x4.z; xv[3] = x4.w;
                xv[4] = x2.x; xv[5] = x2.y;
                #pragma unroll
                for (int kw = 0; kw < 3; kw++) {
                    const float4 wa  = *(const float4*)&ws[cc][kh * 3 + kw][ty * 8];
                    const float4 wb4 = *(const float4*)&ws[cc][kh * 3 + kw][ty * 8 + 4];
                    const float w8[8] = {wa.x, wa.y, wa.z, wa.w, wb4.x, wb4.y, wb4.z, wb4.w};
                    #pragma unroll
                    for (int oo = 0; oo < 8; oo++)
                        #pragma unroll
                        for (int j = 0; j < 4; j++)
                            acc[oo][j] = fmaf(w8[oo], xv[j + kw], acc[oo][j]);
                }
            }
        }
        __syncthreads();
    }

    float* ob = out + ((size_t)b * NO) * PLANE + (size_t)h * NW + tx * 4;
    #pragma unroll
    for (int oo = 0; oo < 8; oo++) {
        const int o = ty * 8 + oo;
        float4 r = make_float4(acc[oo][0], acc[oo][1], acc[oo][2], acc[oo][3]);
        *(float4*)&ob[(size_t)o * PLANE] = r;
    }
}

// ---------------------------------------------------------------------------
extern "C" void kernel_launch(void* const* d_in, const int* in_sizes, int n_in,
                              void* d_out, int out_size) {
    const float* x      = (const float*)d_in[0];
    const float* scale  = (const float*)d_in[1];
    const float* rw1    = (const float*)d_in[2];
    const float* rb1    = (const float*)d_in[3];
    const float* rw2    = (const float*)d_in[4];
    const float* rb2    = (const float*)d_in[5];
    const float* fc_w   = (const float*)d_in[6];
    const float* bn_g   = (const float*)d_in[7];
    const float* bn_b   = (const float*)d_in[8];
    const float* bn_m   = (const float*)d_in[9];
    const float* bn_v   = (const float*)d_in[10];
    const float* cfc_w  = (const float*)d_in[11];
    const float* cfc_b  = (const float*)d_in[12];
    const float* ffc_w  = (const float*)d_in[13];
    const float* ffc_b  = (const float*)d_in[14];
    const float* sfc_w  = (const float*)d_in[15];
    const float* sfc_b  = (const float*)d_in[16];
    const float* kfc_w  = (const float*)d_in[17];
    const float* kfc_b  = (const float*)d_in[18];
    const float* weight = (const float*)d_in[19];
    float* out = (float*)d_out;

    gap_kernel<<<NB * NC, 256>>>(x);
    att_kernel<<<NB, 128>>>(scale, rw1, rb1, rw2, rb2, fc_w,
                            bn_g, bn_b, bn_m, bn_v,
                            cfc_w, cfc_b, ffc_w, ffc_b,
                            sfc_w, sfc_b, kfc_w, kfc_b);
    wprep_kernel<<<NB * NO, 288>>>(weight);
    dim3 grid(NH, NB);
    dim3 blk(40, 8);
    conv_kernel<<<grid, blk>>>(x, out);
}

// round 2
// speedup vs baseline: 1.3381x; 1.3381x over previous
#include <cuda_runtime.h>
#include <math.h>

// Problem constants
#define NB 16
#define NC 64
#define NO 64
#define NH 160
#define NW 160
#define NK 8
#define NA 16
#define KHW 9
#define PLANE (NH*NW)          // 25600
#define CC 8                   // c-chunk in conv

// Scratch (device globals; no allocation allowed)
__device__ float g_gap [NB*NC];
__device__ float g_chan[NB*NC];
__device__ float g_filt[NB*NO];
__device__ float g_spat[NB*KHW];
__device__ float g_katt[NB*NK];
__device__ float g_W   [NB*NC*KHW*NO];   // [b][c][khw][o], gates folded in

// ---------------------------------------------------------------------------
// 1) Global average pool: one block per (b,c) plane
// ---------------------------------------------------------------------------
__global__ void gap_kernel(const float* __restrict__ x) {
    const int plane = blockIdx.x;                       // b*64 + c
    const float4* xp = (const float4*)(x + (size_t)plane * PLANE);
    float s = 0.f;
    for (int i = threadIdx.x; i < PLANE / 4; i += 256) {
        float4 v = xp[i];
        s += (v.x + v.y) + (v.z + v.w);
    }
    #pragma unroll
    for (int off = 16; off; off >>= 1) s += __shfl_down_sync(0xffffffffu, s, off);
    __shared__ float sm[8];
    if ((threadIdx.x & 31) == 0) sm[threadIdx.x >> 5] = s;
    __syncthreads();
    if (threadIdx.x == 0) {
        float t = 0.f;
        #pragma unroll
        for (int i = 0; i < 8; i++) t += sm[i];
        g_gap[plane] = t * (1.f / (float)PLANE);
    }
}

// ---------------------------------------------------------------------------
// 2) Routing MLP + BN + 4 attention heads: one block (128 thr) per batch b
// ---------------------------------------------------------------------------
__global__ void att_kernel(const float* __restrict__ scale,
                           const float* __restrict__ rw1, const float* __restrict__ rb1,
                           const float* __restrict__ rw2, const float* __restrict__ rb2,
                           const float* __restrict__ fc_w,
                           const float* __restrict__ bn_g, const float* __restrict__ bn_b,
                           const float* __restrict__ bn_m, const float* __restrict__ bn_v,
                           const float* __restrict__ cfc_w, const float* __restrict__ cfc_b,
                           const float* __restrict__ ffc_w, const float* __restrict__ ffc_b,
                           const float* __restrict__ sfc_w, const float* __restrict__ sfc_b,
                           const float* __restrict__ kfc_w, const float* __restrict__ kfc_b) {
    const int b = blockIdx.x;
    const int t = threadIdx.x;
    __shared__ float s[66], h1[128], rt[64], v[16], kl[8];

    if (t < 2)       s[t] = 1.f / scale[t];
    else if (t < 66) s[t] = g_gap[b * NC + (t - 2)];
    __syncthreads();

    {   // layer 1: [128,66]
        float a = rb1[t];
        #pragma unroll 6
        for (int i = 0; i < 66; i++) a += rw1[t * 66 + i] * s[i];
        h1[t] = fmaxf(a, 0.f);
    }
    __syncthreads();
    if (t < 64) {   // layer 2: [64,128]
        float a = rb2[t];
        #pragma unroll 8
        for (int i = 0; i < 128; i++) a += rw2[t * 128 + i] * h1[i];
        rt[t] = fmaxf(a, 0.f);
    }
    __syncthreads();
    if (t < NA) {   // trunk: fc (no bias) + BN(eval) + relu
        float a = 0.f;
        #pragma unroll 8
        for (int i = 0; i < 64; i++) a += fc_w[t * 64 + i] * rt[i];
        a = (a - bn_m[t]) * rsqrtf(bn_v[t] + 1e-5f) * bn_g[t] + bn_b[t];
        v[t] = fmaxf(a, 0.f);
    }
    __syncthreads();
    if (t < 64) {
        float a = cfc_b[t], f = ffc_b[t];
        #pragma unroll
        for (int i = 0; i < NA; i++) { a += cfc_w[t * NA + i] * v[i]; f += ffc_w[t * NA + i] * v[i]; }
        g_chan[b * NC + t] = 1.f / (1.f + expf(-a));
        g_filt[b * NO + t] = 1.f / (1.f + expf(-f));
    }
    if (t < KHW) {
        float a = sfc_b[t];
        #pragma unroll
        for (int i = 0; i < NA; i++) a += sfc_w[t * NA + i] * v[i];
        g_spat[b * KHW + t] = 1.f / (1.f + expf(-a));
    }
    if (t < NK) {
        float a = kfc_b[t];
        #pragma unroll
        for (int i = 0; i < NA; i++) a += kfc_w[t * NA + i] * v[i];
        kl[t] = a;
    }
    __syncthreads();
    if (t == 0) {   // softmax over 8 experts
        float m = kl[0];
        #pragma unroll
        for (int i = 1; i < NK; i++) m = fmaxf(m, kl[i]);
        float e[NK], sum = 0.f;
        #pragma unroll
        for (int i = 0; i < NK; i++) { e[i] = expf(kl[i] - m); sum += e[i]; }
        float inv = 1.f / sum;
        #pragma unroll
        for (int i = 0; i < NK; i++) g_katt[b * NK + i] = e[i] * inv;
    }
}

// ---------------------------------------------------------------------------
// 3) Per-sample aggregated weights with all gates folded in.
//    Block = (b, o); threads stride over e = c*9+khw (coalesced weight reads).
//    g_W layout: [b][c][khw][o]  (o contiguous -> conv reads via float4)
// ---------------------------------------------------------------------------
__global__ void wprep_kernel(const float* __restrict__ weight) {
    const int b = blockIdx.x >> 6;
    const int o = blockIdx.x & 63;
    __shared__ float ka[NK], sp[KHW], ch[NC], fo;
    const int t = threadIdx.x;
    if (t < NK)               ka[t]      = g_katt[b * NK + t];
    else if (t < NK + KHW)    sp[t - NK] = g_spat[b * KHW + (t - NK)];
    else if (t < NK + KHW + NC) ch[t - NK - KHW] = g_chan[b * NC + (t - NK - KHW)];
    else if (t == NK + KHW + NC) fo = g_filt[b * NO + o];
    __syncthreads();

    const float* wo = weight + (size_t)o * (NC * KHW);     // + k*NO*NC*KHW
    for (int e = t; e < NC * KHW; e += blockDim.x) {
        float a = 0.f;
        #pragma unroll
        for (int k = 0; k < NK; k++)
            a += ka[k] * wo[(size_t)k * NO * NC * KHW + e];
        const int c = e / KHW, khw = e - c * KHW;
        g_W[(((size_t)b * NC + c) * KHW + khw) * NO + o] = a * fo * ch[c] * sp[khw];
    }
}

// ---------------------------------------------------------------------------
// 4) Conv: block = (output row h, batch b). 64 o x 160 px per block.
//    threads (40,8): tx -> 4 contiguous cols, ty -> 8 output channels.
//    SMEM-chunked over c (CC=8). Register tile 8o x 4px = 32 FMAs per
//    (c,kh,kw) step per thread -> FFMA-issue bound, not LDS bound.
// ---------------------------------------------------------------------------
__global__ __launch_bounds__(320, 2)
void conv_kernel(const float* __restrict__ x, float* __restrict__ out) {
    const int h  = blockIdx.x;
    const int b  = blockIdx.y;
    const int tx = threadIdx.x;     // 0..39
    const int ty = threadIdx.y;     // 0..7
    const int tid = ty * 40 + tx;

    __shared__ __align__(16) float xs[CC][3][164];   // cols: input col = i-1 (zero pad)
    __shared__ __align__(16) float ws[CC][KHW][NO];

    float acc[8][4];
    #pragma unroll
    for (int i = 0; i < 8; i++)
        #pragma unroll
        for (int j = 0; j < 4; j++) acc[i][j] = 0.f;

    const float* xb = x   + (size_t)b * NC * PLANE;
    const float* wb = g_W + (size_t)b * NC * KHW * NO;

    for (int c0 = 0; c0 < NC; c0 += CC) {
        // --- load x chunk (rows h-1..h+1, cols -1..160 zero-padded) ---
        for (int e = tid; e < CC * 3 * 164; e += 320) {
            const int cc  = e / (3 * 164);
            const int rem = e - cc * (3 * 164);
            const int kh  = rem / 164;
            const int i   = rem - kh * 164;
            const int row = h - 1 + kh;
            const int col = i - 1;
            float val = 0.f;
            if (i < 162 && (unsigned)col < NW && (unsigned)row < NH)
                val = xb[(size_t)(c0 + cc) * PLANE + row * NW + col];
            xs[cc][kh][i] = val;
        }
        // --- load weight chunk (contiguous in g_W) ---
        for (int e = tid; e < CC * KHW * NO; e += 320)
            ((float*)ws)[e] = wb[(size_t)c0 * KHW * NO + e];
        __syncthreads();

        for (int cc = 0; cc < CC; cc++) {
            #pragma unroll
            for (int kh = 0; kh < 3; kh++) {
                float xv[6];
                const float4 x4 = *(const float4*)&xs[cc][kh][tx * 4];
                const float2 x2 = *(const float2*)&xs[cc][kh][tx * 4 + 4];
                xv[0] = x4.x; xv[1] = x4.y; xv[2] = x4.z; xv[3] = x4.w;
                xv[4] = x2.x; xv[5] = x2.y;
                #pragma unroll
                for (int kw = 0; kw < 3; kw++) {
                    const float4 wa  = *(const float4*)&ws[cc][kh * 3 + kw][ty * 8];
                    const float4 wb4 = *(const float4*)&ws[cc][kh * 3 + kw][ty * 8 + 4];
                    const float w8[8] = {wa.x, wa.y, wa.z, wa.w, wb4.x, wb4.y, wb4.z, wb4.w};
                    #pragma unroll
                    for (int oo = 0; oo < 8; oo++)
                        #pragma unroll
                        for (int j = 0; j < 4; j++)
                            acc[oo][j] = fmaf(w8[oo], xv[j + kw], acc[oo][j]);
                }
            }
        }
        __syncthreads();
    }

    float* ob = out + ((size_t)b * NO) * PLANE + (size_t)h * NW + tx * 4;
    #pragma unroll
    for (int oo = 0; oo < 8; oo++) {
        const int o = ty * 8 + oo;
        float4 r = make_float4(acc[oo][0], acc[oo][1], acc[oo][2], acc[oo][3]);
        *(float4*)&ob[(size_t)o * PLANE] = r;
    }
}

// ---------------------------------------------------------------------------
extern "C" void kernel_launch(void* const* d_in, const int* in_sizes, int n_in,
                              void* d_out, int out_size) {
    const float* x      = (const float*)d_in[0];
    const float* scale  = (const float*)d_in[1];
    const float* rw1    = (const float*)d_in[2];
    const float* rb1    = (const float*)d_in[3];
    const float* rw2    = (const float*)d_in[4];
    const float* rb2    = (const float*)d_in[5];
    const float* fc_w   = (const float*)d_in[6];
    const float* bn_g   = (const float*)d_in[7];
    const float* bn_b   = (const float*)d_in[8];
    const float* bn_m   = (const float*)d_in[9];
    const float* bn_v   = (const float*)d_in[10];
    const float* cfc_w  = (const float*)d_in[11];
    const float* cfc_b  = (const float*)d_in[12];
    const float* ffc_w  = (const float*)d_in[13];
    const float* ffc_b  = (const float*)d_in[14];
    const float* sfc_w  = (const float*)d_in[15];
    const float* sfc_b  = (const float*)d_in[16];
    const float* kfc_w  = (const float*)d_in[17];
    const float* kfc_b  = (const float*)d_in[18];
    const float* weight = (const float*)d_in[19];
    float* out = (float*)d_out;

    gap_kernel<<<NB * NC, 256>>>(x);
    att_kernel<<<NB, 128>>>(scale, rw1, rb1, rw2, rb2, fc_w,
                            bn_g, bn_b, bn_m, bn_v,
                            cfc_w, cfc_b, ffc_w, ffc_b,
                            sfc_w, sfc_b, kfc_w, kfc_b);
    wprep_kernel<<<NB * NO, 288>>>(weight);
    dim3 grid(NH, NB);
    dim3 blk(40, 8);
    conv_kernel<<<grid, blk>>>(x, out);
}

// round 3
// speedup vs baseline: 1.4232x; 1.0636x over previous
#include <cuda_runtime.h>
#include <math.h>

// Problem constants
#define NB 16
#define NC 64
#define NO 64
#define NH 160
#define NW 160
#define NK 8
#define NA 16
#define KHW 9
#define PLANE (NH*NW)          // 25600
#define CC 8                   // c-chunk in conv

// Scratch (device globals; no allocation allowed)
__device__ float g_gap [NB*NC];
__device__ float g_chan[NB*NC];
__device__ float g_filt[NB*NO];
__device__ float g_spat[NB*KHW];
__device__ float g_katt[NB*NK];
__device__ float g_W   [NB*NC*KHW*NO];   // [b][c][khw][o], gates folded in

// ---- packed fp32x2 helpers (Blackwell sm_103a) ------------------------------
__device__ __forceinline__ void ffma2(unsigned long long& d,
                                      unsigned long long a,
                                      unsigned long long b) {
    asm("fma.rn.f32x2 %0, %1, %2, %0;" : "+l"(d) : "l"(a), "l"(b));
}
__device__ __forceinline__ unsigned long long bcast2(float v) {
    unsigned long long r;
    asm("mov.b64 %0, {%1, %1};" : "=l"(r) : "f"(v));
    return r;
}
__device__ __forceinline__ float2 unpack2(unsigned long long v) {
    float2 r;
    asm("mov.b64 {%0, %1}, %2;" : "=f"(r.x), "=f"(r.y) : "l"(v));
    return r;
}

// ---------------------------------------------------------------------------
// 1) Global average pool: one block per (b,c) plane
// ---------------------------------------------------------------------------
__global__ void gap_kernel(const float* __restrict__ x) {
    const int plane = blockIdx.x;                       // b*64 + c
    const float4* xp = (const float4*)(x + (size_t)plane * PLANE);
    float s = 0.f;
    for (int i = threadIdx.x; i < PLANE / 4; i += 256) {
        float4 v = xp[i];
        s += (v.x + v.y) + (v.z + v.w);
    }
    #pragma unroll
    for (int off = 16; off; off >>= 1) s += __shfl_down_sync(0xffffffffu, s, off);
    __shared__ float sm[8];
    if ((threadIdx.x & 31) == 0) sm[threadIdx.x >> 5] = s;
    __syncthreads();
    if (threadIdx.x == 0) {
        float t = 0.f;
        #pragma unroll
        for (int i = 0; i < 8; i++) t += sm[i];
        g_gap[plane] = t * (1.f / (float)PLANE);
    }
}

// ---------------------------------------------------------------------------
// 2) Routing MLP + BN + 4 attention heads: one block (128 thr) per batch b
// ---------------------------------------------------------------------------
__global__ void att_kernel(const float* __restrict__ scale,
                           const float* __restrict__ rw1, const float* __restrict__ rb1,
                           const float* __restrict__ rw2, const float* __restrict__ rb2,
                           const float* __restrict__ fc_w,
                           const float* __restrict__ bn_g, const float* __restrict__ bn_b,
                           const float* __restrict__ bn_m, const float* __restrict__ bn_v,
                           const float* __restrict__ cfc_w, const float* __restrict__ cfc_b,
                           const float* __restrict__ ffc_w, const float* __restrict__ ffc_b,
                           const float* __restrict__ sfc_w, const float* __restrict__ sfc_b,
                           const float* __restrict__ kfc_w, const float* __restrict__ kfc_b) {
    const int b = blockIdx.x;
    const int t = threadIdx.x;
    __shared__ float s[66], h1[128], rt[64], v[16], kl[8];

    if (t < 2)       s[t] = 1.f / scale[t];
    else if (t < 66) s[t] = g_gap[b * NC + (t - 2)];
    __syncthreads();

    {   // layer 1: [128,66]
        float a = rb1[t];
        #pragma unroll 6
        for (int i = 0; i < 66; i++) a += rw1[t * 66 + i] * s[i];
        h1[t] = fmaxf(a, 0.f);
    }
    __syncthreads();
    if (t < 64) {   // layer 2: [64,128]
        float a = rb2[t];
        #pragma unroll 8
        for (int i = 0; i < 128; i++) a += rw2[t * 128 + i] * h1[i];
        rt[t] = fmaxf(a, 0.f);
    }
    __syncthreads();
    if (t < NA) {   // trunk: fc (no bias) + BN(eval) + relu
        float a = 0.f;
        #pragma unroll 8
        for (int i = 0; i < 64; i++) a += fc_w[t * 64 + i] * rt[i];
        a = (a - bn_m[t]) * rsqrtf(bn_v[t] + 1e-5f) * bn_g[t] + bn_b[t];
        v[t] = fmaxf(a, 0.f);
    }
    __syncthreads();
    if (t < 64) {
        float a = cfc_b[t], f = ffc_b[t];
        #pragma unroll
        for (int i = 0; i < NA; i++) { a += cfc_w[t * NA + i] * v[i]; f += ffc_w[t * NA + i] * v[i]; }
        g_chan[b * NC + t] = 1.f / (1.f + expf(-a));
        g_filt[b * NO + t] = 1.f / (1.f + expf(-f));
    }
    if (t < KHW) {
        float a = sfc_b[t];
        #pragma unroll
        for (int i = 0; i < NA; i++) a += sfc_w[t * NA + i] * v[i];
        g_spat[b * KHW + t] = 1.f / (1.f + expf(-a));
    }
    if (t < NK) {
        float a = kfc_b[t];
        #pragma unroll
        for (int i = 0; i < NA; i++) a += kfc_w[t * NA + i] * v[i];
        kl[t] = a;
    }
    __syncthreads();
    if (t == 0) {   // softmax over 8 experts
        float m = kl[0];
        #pragma unroll
        for (int i = 1; i < NK; i++) m = fmaxf(m, kl[i]);
        float e[NK], sum = 0.f;
        #pragma unroll
        for (int i = 0; i < NK; i++) { e[i] = expf(kl[i] - m); sum += e[i]; }
        float inv = 1.f / sum;
        #pragma unroll
        for (int i = 0; i < NK; i++) g_katt[b * NK + i] = e[i] * inv;
    }
}

// ---------------------------------------------------------------------------
// 3) Per-sample aggregated weights with all gates folded in.
//    g_W layout: [b][c][khw][o]  (o contiguous -> conv reads via LDS.128)
// ---------------------------------------------------------------------------
__global__ void wprep_kernel(const float* __restrict__ weight) {
    const int b = blockIdx.x >> 6;
    const int o = blockIdx.x & 63;
    __shared__ float ka[NK], sp[KHW], ch[NC], fo;
    const int t = threadIdx.x;
    if (t < NK)               ka[t]      = g_katt[b * NK + t];
    else if (t < NK + KHW)    sp[t - NK] = g_spat[b * KHW + (t - NK)];
    else if (t < NK + KHW + NC) ch[t - NK - KHW] = g_chan[b * NC + (t - NK - KHW)];
    else if (t == NK + KHW + NC) fo = g_filt[b * NO + o];
    __syncthreads();

    const float* wo = weight + (size_t)o * (NC * KHW);     // + k*NO*NC*KHW
    for (int e = t; e < NC * KHW; e += blockDim.x) {
        float a = 0.f;
        #pragma unroll
        for (int k = 0; k < NK; k++)
            a += ka[k] * wo[(size_t)k * NO * NC * KHW + e];
        const int c = e / KHW, khw = e - c * KHW;
        g_W[(((size_t)b * NC + c) * KHW + khw) * NO + o] = a * fo * ch[c] * sp[khw];
    }
}

// ---------------------------------------------------------------------------
// 4) Conv with packed fp32x2 FMA. Block = (row h, batch b): 64 o x 160 px.
//    threads (40,8): tx -> 4 cols, ty -> 8 output channels (4 oo-pairs).
//    fp32 lanes paired over adjacent output channels: weight pairs come
//    directly from LDS.128 (ulonglong2), x needs one broadcast pack per value.
// ---------------------------------------------------------------------------
__global__ __launch_bounds__(320, 2)
void conv_kernel(const float* __restrict__ x, float* __restrict__ out) {
    const int h  = blockIdx.x;
    const int b  = blockIdx.y;
    const int tx = threadIdx.x;     // 0..39
    const int ty = threadIdx.y;     // 0..7
    const int tid = ty * 40 + tx;

    __shared__ __align__(16) float xs[CC][3][164];   // cols: input col = i-1 (zero pad)
    __shared__ __align__(16) float ws[CC][KHW][NO];

    unsigned long long acc2[4][4];   // [oo-pair][pixel j], lanes = (o=2op, o=2op+1)
    #pragma unroll
    for (int i = 0; i < 4; i++)
        #pragma unroll
        for (int j = 0; j < 4; j++) acc2[i][j] = 0ULL;

    const float* xb = x   + (size_t)b * NC * PLANE;
    const float* wb = g_W + (size_t)b * NC * KHW * NO;

    for (int c0 = 0; c0 < NC; c0 += CC) {
        // --- load x chunk (rows h-1..h+1, cols -1..160 zero-padded) ---
        for (int e = tid; e < CC * 3 * 164; e += 320) {
            const int cc  = e / (3 * 164);
            const int rem = e - cc * (3 * 164);
            const int kh  = rem / 164;
            const int i   = rem - kh * 164;
            const int row = h - 1 + kh;
            const int col = i - 1;
            float val = 0.f;
            if (i < 162 && (unsigned)col < NW && (unsigned)row < NH)
                val = xb[(size_t)(c0 + cc) * PLANE + row * NW + col];
            xs[cc][kh][i] = val;
        }
        // --- load weight chunk (contiguous in g_W) ---
        for (int e = tid; e < CC * KHW * NO; e += 320)
            ((float*)ws)[e] = wb[(size_t)c0 * KHW * NO + e];
        __syncthreads();

        for (int cc = 0; cc < CC; cc++) {
            #pragma unroll
            for (int kh = 0; kh < 3; kh++) {
                const float4 x4 = *(const float4*)&xs[cc][kh][tx * 4];
                const float2 xt = *(const float2*)&xs[cc][kh][tx * 4 + 4];
                unsigned long long xp[6];
                xp[0] = bcast2(x4.x); xp[1] = bcast2(x4.y);
                xp[2] = bcast2(x4.z); xp[3] = bcast2(x4.w);
                xp[4] = bcast2(xt.x); xp[5] = bcast2(xt.y);
                #pragma unroll
                for (int kw = 0; kw < 3; kw++) {
                    // 8 weights for this (c,kh,kw) as 4 packed oo-pairs, free via LDS.128
                    const ulonglong2 wpa = *(const ulonglong2*)&ws[cc][kh * 3 + kw][ty * 8];
                    const ulonglong2 wpb = *(const ulonglong2*)&ws[cc][kh * 3 + kw][ty * 8 + 4];
                    const unsigned long long wp[4] = {wpa.x, wpa.y, wpb.x, wpb.y};
                    #pragma unroll
                    for (int op = 0; op < 4; op++)
                        #pragma unroll
                        for (int j = 0; j < 4; j++)
                            ffma2(acc2[op][j], wp[op], xp[j + kw]);
                }
            }
        }
        __syncthreads();
    }

    float* ob = out + ((size_t)b * NO) * PLANE + (size_t)h * NW + tx * 4;
    #pragma unroll
    for (int op = 0; op < 4; op++) {
        float4 r0, r1;
        float2 u;
        u = unpack2(acc2[op][0]); r0.x = u.x; r1.x = u.y;
        u = unpack2(acc2[op][1]); r0.y = u.x; r1.y = u.y;
        u = unpack2(acc2[op][2]); r0.z = u.x; r1.z = u.y;
        u = unpack2(acc2[op][3]); r0.w = u.x; r1.w = u.y;
        const int o0 = ty * 8 + 2 * op;
        *(float4*)&ob[(size_t)(o0    ) * PLANE] = r0;
        *(float4*)&ob[(size_t)(o0 + 1) * PLANE] = r1;
    }
}

// ---------------------------------------------------------------------------
extern "C" void kernel_launch(void* const* d_in, const int* in_sizes, int n_in,
                              void* d_out, int out_size) {
    const float* x      = (const float*)d_in[0];
    const float* scale  = (const float*)d_in[1];
    const float* rw1    = (const float*)d_in[2];
    const float* rb1    = (const float*)d_in[3];
    const float* rw2    = (const float*)d_in[4];
    const float* rb2    = (const float*)d_in[5];
    const float* fc_w   = (const float*)d_in[6];
    const float* bn_g   = (const float*)d_in[7];
    const float* bn_b   = (const float*)d_in[8];
    const float* bn_m   = (const float*)d_in[9];
    const float* bn_v   = (const float*)d_in[10];
    const float* cfc_w  = (const float*)d_in[11];
    const float* cfc_b  = (const float*)d_in[12];
    const float* ffc_w  = (const float*)d_in[13];
    const float* ffc_b  = (const float*)d_in[14];
    const float* sfc_w  = (const float*)d_in[15];
    const float* sfc_b  = (const float*)d_in[16];
    const float* kfc_w  = (const float*)d_in[17];
    const float* kfc_b  = (const float*)d_in[18];
    const float* weight = (const float*)d_in[19];
    float* out = (float*)d_out;

    gap_kernel<<<NB * NC, 256>>>(x);
    att_kernel<<<NB, 128>>>(scale, rw1, rb1, rw2, rb2, fc_w,
                            bn_g, bn_b, bn_m, bn_v,
                            cfc_w, cfc_b, ffc_w, ffc_b,
                            sfc_w, sfc_b, kfc_w, kfc_b);
    wprep_kernel<<<NB * NO, 288>>>(weight);
    dim3 grid(NH, NB);
    dim3 blk(40, 8);
    conv_kernel<<<grid, blk>>>(x, out);
}

// round 5
// speedup vs baseline: 2.4631x; 1.7307x over previous
#include <cuda_runtime.h>
#include <cstdint>
#include <math.h>

// Problem constants
#define NB 16
#define NC 64
#define NO 64
#define NH 160
#define NW 160
#define NK 8
#define NA 16
#define KHW 9
#define PLANE (NH*NW)          // 25600
#define CC 8                   // c-chunk in conv
#define XPAD 168               // xs row pad (floats)
#define WPAD 72                // ws o-dim pad (floats)

// Scratch (device globals; no allocation allowed)
__device__ float g_gap [NB*NC];
__device__ float g_chan[NB*NC];
__device__ float g_filt[NB*NO];
__device__ float g_spat[NB*KHW];
__device__ float g_katt[NB*NK];
__device__ float g_W   [NB*NC*KHW*NO];   // [b][c][khw][o], gates folded, tf32-rounded

// ---- tf32 helpers -----------------------------------------------------------
__device__ __forceinline__ uint32_t to_tf32(float v) {
    uint32_t r;
    asm("cvt.rna.tf32.f32 %0, %1;" : "=r"(r) : "f"(v));
    return r;
}
__device__ __forceinline__ void mma8(float* d, const uint32_t* a, const uint32_t* b) {
    asm volatile(
        "mma.sync.aligned.m16n8k8.row.col.f32.tf32.tf32.f32 "
        "{%0,%1,%2,%3}, {%4,%5,%6,%7}, {%8,%9}, {%0,%1,%2,%3};"
        : "+f"(d[0]), "+f"(d[1]), "+f"(d[2]), "+f"(d[3])
        : "r"(a[0]), "r"(a[1]), "r"(a[2]), "r"(a[3]), "r"(b[0]), "r"(b[1]));
}

// ---------------------------------------------------------------------------
// 1) Global average pool: one block per (b,c) plane
// ---------------------------------------------------------------------------
__global__ void gap_kernel(const float* __restrict__ x) {
    const int plane = blockIdx.x;                       // b*64 + c
    const float4* xp = (const float4*)(x + (size_t)plane * PLANE);
    float s = 0.f;
    for (int i = threadIdx.x; i < PLANE / 4; i += 256) {
        float4 v = xp[i];
        s += (v.x + v.y) + (v.z + v.w);
    }
    #pragma unroll
    for (int off = 16; off; off >>= 1) s += __shfl_down_sync(0xffffffffu, s, off);
    __shared__ float sm[8];
    if ((threadIdx.x & 31) == 0) sm[threadIdx.x >> 5] = s;
    __syncthreads();
    if (threadIdx.x == 0) {
        float t = 0.f;
        #pragma unroll
        for (int i = 0; i < 8; i++) t += sm[i];
        g_gap[plane] = t * (1.f / (float)PLANE);
    }
}

// ---------------------------------------------------------------------------
// 2) Routing MLP + BN + 4 attention heads: one block (128 thr) per batch b
// ---------------------------------------------------------------------------
__global__ void att_kernel(const float* __restrict__ scale,
                           const float* __restrict__ rw1, const float* __restrict__ rb1,
                           const float* __restrict__ rw2, const float* __restrict__ rb2,
                           const float* __restrict__ fc_w,
                           const float* __restrict__ bn_g, const float* __restrict__ bn_b,
                           const float* __restrict__ bn_m, const float* __restrict__ bn_v,
                           const float* __restrict__ cfc_w, const float* __restrict__ cfc_b,
                           const float* __restrict__ ffc_w, const float* __restrict__ ffc_b,
                           const float* __restrict__ sfc_w, const float* __restrict__ sfc_b,
                           const float* __restrict__ kfc_w, const float* __restrict__ kfc_b) {
    const int b = blockIdx.x;
    const int t = threadIdx.x;
    __shared__ float s[66], h1[128], rt[64], v[16], kl[8];

    if (t < 2)       s[t] = 1.f / scale[t];
    else if (t < 66) s[t] = g_gap[b * NC + (t - 2)];
    __syncthreads();
    {   // layer 1: [128,66]
        float a = rb1[t];
        #pragma unroll 6
        for (int i = 0; i < 66; i++) a += rw1[t * 66 + i] * s[i];
        h1[t] = fmaxf(a, 0.f);
    }
    __syncthreads();
    if (t < 64) {   // layer 2: [64,128]
        float a = rb2[t];
        #pragma unroll 8
        for (int i = 0; i < 128; i++) a += rw2[t * 128 + i] * h1[i];
        rt[t] = fmaxf(a, 0.f);
    }
    __syncthreads();
    if (t < NA) {   // trunk: fc (no bias) + BN(eval) + relu
        float a = 0.f;
        #pragma unroll 8
        for (int i = 0; i < 64; i++) a += fc_w[t * 64 + i] * rt[i];
        a = (a - bn_m[t]) * rsqrtf(bn_v[t] + 1e-5f) * bn_g[t] + bn_b[t];
        v[t] = fmaxf(a, 0.f);
    }
    __syncthreads();
    if (t < 64) {
        float a = cfc_b[t], f = ffc_b[t];
        #pragma unroll
        for (int i = 0; i < NA; i++) { a += cfc_w[t * NA + i] * v[i]; f += ffc_w[t * NA + i] * v[i]; }
        g_chan[b * NC + t] = 1.f / (1.f + expf(-a));
        g_filt[b * NO + t] = 1.f / (1.f + expf(-f));
    }
    if (t < KHW) {
        float a = sfc_b[t];
        #pragma unroll
        for (int i = 0; i < NA; i++) a += sfc_w[t * NA + i] * v[i];
        g_spat[b * KHW + t] = 1.f / (1.f + expf(-a));
    }
    if (t < NK) {
        float a = kfc_b[t];
        #pragma unroll
        for (int i = 0; i < NA; i++) a += kfc_w[t * NA + i] * v[i];
        kl[t] = a;
    }
    __syncthreads();
    if (t == 0) {   // softmax over 8 experts
        float m = kl[0];
        #pragma unroll
        for (int i = 1; i < NK; i++) m = fmaxf(m, kl[i]);
        float e[NK], sum = 0.f;
        #pragma unroll
        for (int i = 0; i < NK; i++) { e[i] = expf(kl[i] - m); sum += e[i]; }
        float inv = 1.f / sum;
        #pragma unroll
        for (int i = 0; i < NK; i++) g_katt[b * NK + i] = e[i] * inv;
    }
}

// ---------------------------------------------------------------------------
// 3) Per-sample aggregated weights, gates folded, tf32-rounded.
//    g_W layout: [b][c][khw][o]
// ---------------------------------------------------------------------------
__global__ void wprep_kernel(const float* __restrict__ weight) {
    const int b = blockIdx.x >> 6;
    const int o = blockIdx.x & 63;
    __shared__ float ka[NK], sp[KHW], ch[NC], fo;
    const int t = threadIdx.x;
    if (t < NK)                 ka[t]      = g_katt[b * NK + t];
    else if (t < NK + KHW)      sp[t - NK] = g_spat[b * KHW + (t - NK)];
    else if (t < NK + KHW + NC) ch[t - NK - KHW] = g_chan[b * NC + (t - NK - KHW)];
    else if (t == NK + KHW + NC) fo = g_filt[b * NO + o];
    __syncthreads();

    const float* wo = weight + (size_t)o * (NC * KHW);
    for (int e = t; e < NC * KHW; e += blockDim.x) {
        float a = 0.f;
        #pragma unroll
        for (int k = 0; k < NK; k++)
            a += ka[k] * wo[(size_t)k * NO * NC * KHW + e];
        const int c = e / KHW, khw = e - c * KHW;
        const float val = a * fo * ch[c] * sp[khw];
        const uint32_t bits = to_tf32(val);
        g_W[(((size_t)b * NC + c) * KHW + khw) * NO + o] = __uint_as_float(bits);
    }
}

// ---------------------------------------------------------------------------
// 4) Conv as tf32 mma.sync implicit GEMM.
//    Block = (row h, batch b). GEMM: M=160 px, N=64 o, K=576 (tap x c).
//    320 thr = 10 warps = 5 M-groups x 2 N-groups; warp tile M=32 x N=32.
//    K processed as 8 c-chunks x 9 taps, k-step = 8 channels.
// ---------------------------------------------------------------------------
__global__ __launch_bounds__(320, 2)
void conv_kernel(const float* __restrict__ x, float* __restrict__ out) {
    __shared__ uint32_t xs[CC][3][XPAD];        // tf32 bits; col i = input col i-1
    __shared__ uint32_t ws[KHW][CC][WPAD];      // [tap][c][o], padded rows

    const int h    = blockIdx.x;
    const int b    = blockIdx.y;
    const int tid  = threadIdx.x;
    const int lane = tid & 31;
    const int warp = tid >> 5;                  // 0..9
    const int mw   = (warp % 5) * 32;           // pixel base
    const int nw   = (warp / 5) * 32;           // o base
    const int lg   = lane >> 2;                 // 0..7
    const int lk   = lane & 3;                  // 0..3

    float acc[2][4][4];
    #pragma unroll
    for (int i = 0; i < 2; i++)
        #pragma unroll
        for (int j = 0; j < 4; j++)
            #pragma unroll
            for (int k = 0; k < 4; k++) acc[i][j][k] = 0.f;

    const float* xb = x   + (size_t)b * NC * PLANE;
    const float* wb = g_W + (size_t)b * NC * KHW * NO;

    for (int c0 = 0; c0 < NC; c0 += CC) {
        // --- stage x chunk (rows h-1..h+1, cols -1..160 zero-padded), tf32 ---
        for (int e = tid; e < CC * 3 * 164; e += 320) {
            const int cc  = e / (3 * 164);
            const int rem = e - cc * (3 * 164);
            const int kh  = rem / 164;
            const int i   = rem - kh * 164;
            const int row = h - 1 + kh;
            const int col = i - 1;
            float val = 0.f;
            if (i < 162 && (unsigned)col < NW && (unsigned)row < NH)
                val = xb[(size_t)(c0 + cc) * PLANE + row * NW + col];
            xs[cc][kh][i] = to_tf32(val);
        }
        // --- stage weight chunk: ws[tap][cc][o] from g_W[b][c][tap][o] ---
        for (int e = tid; e < CC * KHW * NO; e += 320) {
            const int cc  = e / (KHW * NO);
            const int rem = e - cc * (KHW * NO);
            const int tap = rem / NO;
            const int o   = rem - tap * NO;
            ws[tap][cc][o] = __float_as_uint(wb[(size_t)(c0 + cc) * KHW * NO + rem]);
        }
        __syncthreads();

        #pragma unroll
        for (int tap = 0; tap < KHW; tap++) {
            const int kh = tap / 3;
            const int kw = tap - kh * 3;

            uint32_t bf[4][2];
            #pragma unroll
            for (int nt = 0; nt < 4; nt++) {
                const int n = nw + nt * 8 + lg;
                bf[nt][0] = ws[tap][lk][n];
                bf[nt][1] = ws[tap][lk + 4][n];
            }
            uint32_t af[2][4];
            #pragma unroll
            for (int mt = 0; mt < 2; mt++) {
                const int r = mw + mt * 16 + lg + kw;   // xs col = pixel + kw
                af[mt][0] = xs[lk][kh][r];
                af[mt][1] = xs[lk][kh][r + 8];
                af[mt][2] = xs[lk + 4][kh][r];
                af[mt][3] = xs[lk + 4][kh][r + 8];
            }
            #pragma unroll
            for (int mt = 0; mt < 2; mt++)
                #pragma unroll
                for (int nt = 0; nt < 4; nt++)
                    mma8(acc[mt][nt], af[mt], bf[nt]);
        }
        __syncthreads();
    }

    // --- epilogue: d0:(m,n) d1:(m,n+1) d2:(m+8,n) d3:(m+8,n+1) ---
    #pragma unroll
    for (int mt = 0; mt < 2; mt++) {
        const int m = mw + mt * 16 + lg;
        #pragma unroll
        for (int nt = 0; nt < 4; nt++) {
            const int o = nw + nt * 8 + 2 * lk;
            float* ob = out + ((size_t)b * NO + o) * PLANE + (size_t)h * NW;
            ob[m]             = acc[mt][nt][0];
            ob[PLANE + m]     = acc[mt][nt][1];
            ob[m + 8]         = acc[mt][nt][2];
            ob[PLANE + m + 8] = acc[mt][nt][3];
        }
    }
}

// ---------------------------------------------------------------------------
extern "C" void kernel_launch(void* const* d_in, const int* in_sizes, int n_in,
                              void* d_out, int out_size) {
    const float* x      = (const float*)d_in[0];
    const float* scale  = (const float*)d_in[1];
    const float* rw1    = (const float*)d_in[2];
    const float* rb1    = (const float*)d_in[3];
    const float* rw2    = (const float*)d_in[4];
    const float* rb2    = (const float*)d_in[5];
    const float* fc_w   = (const float*)d_in[6];
    const float* bn_g   = (const float*)d_in[7];
    const float* bn_b   = (const float*)d_in[8];
    const float* bn_m   = (const float*)d_in[9];
    const float* bn_v   = (const float*)d_in[10];
    const float* cfc_w  = (const float*)d_in[11];
    const float* cfc_b  = (const float*)d_in[12];
    const float* ffc_w  = (const float*)d_in[13];
    const float* ffc_b  = (const float*)d_in[14];
    const float* sfc_w  = (const float*)d_in[15];
    const float* sfc_b  = (const float*)d_in[16];
    const float* kfc_w  = (const float*)d_in[17];
    const float* kfc_b  = (const float*)d_in[18];
    const float* weight = (const float*)d_in[19];
    float* out = (float*)d_out;

    gap_kernel<<<NB * NC, 256>>>(x);
    att_kernel<<<NB, 128>>>(scale, rw1, rb1, rw2, rb2, fc_w,
                            bn_g, bn_b, bn_m, bn_v,
                            cfc_w, cfc_b, ffc_w, ffc_b,
                            sfc_w, sfc_b, kfc_w, kfc_b);
    wprep_kernel<<<NB * NO, 288>>>(weight);
    dim3 grid(NH, NB);
    conv_kernel<<<grid, 320>>>(x, out);
}

// round 6
// speedup vs baseline: 5.0122x; 2.0349x over previous
#include <cuda_runtime.h>
#include <cuda_fp16.h>
#include <cstdint>
#include <math.h>

// Problem constants
#define NB 16
#define NC 64
#define NO 64
#define NH 160
#define NW 160
#define NK 8
#define NA 16
#define KHW 9
#define PLANE (NH*NW)          // 25600
#define NCH 4                  // channel chunks of 16
#define XS_WORDS (3*162*12)    // 5832 u32 (half2 words, 12-word col stride: 8 data + 4 pad)
#define WS_WORDS (9*64*12)     // 6912 u32
#define SMEM_BYTES ((XS_WORDS + WS_WORDS) * 4)   // 50976

// Scratch (device globals; no allocation allowed)
__device__ float    g_gap [NB*NC];
__device__ float    g_chan[NB*NC];
__device__ float    g_filt[NB*NO];
__device__ float    g_spat[NB*KHW];
__device__ float    g_katt[NB*NK];
__device__ uint32_t g_Wh  [NB*NCH*WS_WORDS];   // pre-packed half2 SMEM image per (b,chunk)

// ---------------------------------------------------------------------------
__device__ __forceinline__ void mma16(float* d, const uint32_t* a, const uint32_t* b) {
    asm volatile(
        "mma.sync.aligned.m16n8k16.row.col.f32.f16.f16.f32 "
        "{%0,%1,%2,%3}, {%4,%5,%6,%7}, {%8,%9}, {%0,%1,%2,%3};"
        : "+f"(d[0]), "+f"(d[1]), "+f"(d[2]), "+f"(d[3])
        : "r"(a[0]), "r"(a[1]), "r"(a[2]), "r"(a[3]), "r"(b[0]), "r"(b[1]));
}

// ---------------------------------------------------------------------------
// 1) Global average pool: one block per (b,c) plane
// ---------------------------------------------------------------------------
__global__ void gap_kernel(const float* __restrict__ x) {
    const int plane = blockIdx.x;                       // b*64 + c
    const float4* xp = (const float4*)(x + (size_t)plane * PLANE);
    float s = 0.f;
    for (int i = threadIdx.x; i < PLANE / 4; i += 256) {
        float4 v = xp[i];
        s += (v.x + v.y) + (v.z + v.w);
    }
    #pragma unroll
    for (int off = 16; off; off >>= 1) s += __shfl_down_sync(0xffffffffu, s, off);
    __shared__ float sm[8];
    if ((threadIdx.x & 31) == 0) sm[threadIdx.x >> 5] = s;
    __syncthreads();
    if (threadIdx.x == 0) {
        float t = 0.f;
        #pragma unroll
        for (int i = 0; i < 8; i++) t += sm[i];
        g_gap[plane] = t * (1.f / (float)PLANE);
    }
}

// ---------------------------------------------------------------------------
// 2) Routing MLP + BN + 4 attention heads: one block (128 thr) per batch b
// ---------------------------------------------------------------------------
__global__ void att_kernel(const float* __restrict__ scale,
                           const float* __restrict__ rw1, const float* __restrict__ rb1,
                           const float* __restrict__ rw2, const float* __restrict__ rb2,
                           const float* __restrict__ fc_w,
                           const float* __restrict__ bn_g, const float* __restrict__ bn_b,
                           const float* __restrict__ bn_m, const float* __restrict__ bn_v,
                           const float* __restrict__ cfc_w, const float* __restrict__ cfc_b,
                           const float* __restrict__ ffc_w, const float* __restrict__ ffc_b,
                           const float* __restrict__ sfc_w, const float* __restrict__ sfc_b,
                           const float* __restrict__ kfc_w, const float* __restrict__ kfc_b) {
    const int b = blockIdx.x;
    const int t = threadIdx.x;
    __shared__ float s[66], h1[128], rt[64], v[16], kl[8];

    if (t < 2)       s[t] = 1.f / scale[t];
    else if (t < 66) s[t] = g_gap[b * NC + (t - 2)];
    __syncthreads();
    {   // layer 1: [128,66]
        float a = rb1[t];
        #pragma unroll 6
        for (int i = 0; i < 66; i++) a += rw1[t * 66 + i] * s[i];
        h1[t] = fmaxf(a, 0.f);
    }
    __syncthreads();
    if (t < 64) {   // layer 2: [64,128]
        float a = rb2[t];
        #pragma unroll 8
        for (int i = 0; i < 128; i++) a += rw2[t * 128 + i] * h1[i];
        rt[t] = fmaxf(a, 0.f);
    }
    __syncthreads();
    if (t < NA) {   // trunk: fc (no bias) + BN(eval) + relu
        float a = 0.f;
        #pragma unroll 8
        for (int i = 0; i < 64; i++) a += fc_w[t * 64 + i] * rt[i];
        a = (a - bn_m[t]) * rsqrtf(bn_v[t] + 1e-5f) * bn_g[t] + bn_b[t];
        v[t] = fmaxf(a, 0.f);
    }
    __syncthreads();
    if (t < 64) {
        float a = cfc_b[t], f = ffc_b[t];
        #pragma unroll
        for (int i = 0; i < NA; i++) { a += cfc_w[t * NA + i] * v[i]; f += ffc_w[t * NA + i] * v[i]; }
        g_chan[b * NC + t] = 1.f / (1.f + expf(-a));
        g_filt[b * NO + t] = 1.f / (1.f + expf(-f));
    }
    if (t < KHW) {
        float a = sfc_b[t];
        #pragma unroll
        for (int i = 0; i < NA; i++) a += sfc_w[t * NA + i] * v[i];
        g_spat[b * KHW + t] = 1.f / (1.f + expf(-a));
    }
    if (t < NK) {
        float a = kfc_b[t];
        #pragma unroll
        for (int i = 0; i < NA; i++) a += kfc_w[t * NA + i] * v[i];
        kl[t] = a;
    }
    __syncthreads();
    if (t == 0) {   // softmax over 8 experts
        float m = kl[0];
        #pragma unroll
        for (int i = 1; i < NK; i++) m = fmaxf(m, kl[i]);
        float e[NK], sum = 0.f;
        #pragma unroll
        for (int i = 0; i < NK; i++) { e[i] = expf(kl[i] - m); sum += e[i]; }
        float inv = 1.f / sum;
        #pragma unroll
        for (int i = 0; i < NK; i++) g_katt[b * NK + i] = e[i] * inv;
    }
}

// ---------------------------------------------------------------------------
// 3) Aggregated+gated weights -> half2-packed padded SMEM image.
//    g_Wh[b][chunk][tap][o][word 0..11]: word w = half2(c = 2w, 2w+1) of the
//    16-channel chunk; words 8..11 are pad (never read by MMA).
// ---------------------------------------------------------------------------
__global__ void wprep_kernel(const float* __restrict__ weight) {
    const int b = blockIdx.x >> 6;
    const int o = blockIdx.x & 63;
    __shared__ float ka[NK], sp[KHW], ch[NC], fo;
    const int t = threadIdx.x;
    if (t < NK)                 ka[t]      = g_katt[b * NK + t];
    else if (t < NK + KHW)      sp[t - NK] = g_spat[b * KHW + (t - NK)];
    else if (t < NK + KHW + NC) ch[t - NK - KHW] = g_chan[b * NC + (t - NK - KHW)];
    else if (t == NK + KHW + NC) fo = g_filt[b * NO + o];
    __syncthreads();

    const float* wo = weight + (size_t)o * (NC * KHW);
    // 288 threads = 32 c-pairs x 9 taps, one element each
    const int cp  = t / KHW;         // 0..31
    const int khw = t - cp * KHW;    // 0..8
    const int c0  = 2 * cp;
    float a0 = 0.f, a1 = 0.f;
    #pragma unroll
    for (int k = 0; k < NK; k++) {
        const float* wk = wo + (size_t)k * NO * NC * KHW;
        a0 += ka[k] * wk[c0 * KHW + khw];
        a1 += ka[k] * wk[(c0 + 1) * KHW + khw];
    }
    const float g = fo * sp[khw];
    const __half2 hv = __floats2half2_rn(a0 * g * ch[c0], a1 * g * ch[c0 + 1]);
    const int chunk = cp >> 3;
    const int w     = cp & 7;
    g_Wh[((((size_t)b * NCH + chunk) * KHW + khw) * NO + o) * 12 + w] =
        *(const uint32_t*)&hv;
}

// ---------------------------------------------------------------------------
// 4) Conv as fp16 m16n8k16 implicit GEMM.
//    Block = (row h, batch b). GEMM: M=160 px, N=64 o, K=576 (tap x c).
//    320 thr = 10 warps = 5 M-groups x 2 N-groups; warp tile 32x32.
//    K as 4 chunks of 16 channels x 9 taps; k-step = 16 channels.
//    SMEM col/row stride = 12 words (48B) -> conflict-free fragment loads.
// ---------------------------------------------------------------------------
__global__ __launch_bounds__(320, 2)
void conv_kernel(const float* __restrict__ x, float* __restrict__ out) {
    extern __shared__ __align__(16) uint32_t dsm[];
    uint32_t* xs = dsm;                 // [kh 3][col 162][12]  (col i = input col i-1)
    uint32_t* sw = dsm + XS_WORDS;      // [tap 9][o 64][12]

    const int h    = blockIdx.x;
    const int b    = blockIdx.y;
    const int tid  = threadIdx.x;
    const int lane = tid & 31;
    const int warp = tid >> 5;                  // 0..9
    const int mw   = (warp % 5) * 32;           // pixel base
    const int nw   = (warp / 5) * 32;           // o base
    const int lg   = lane >> 2;                 // 0..7
    const int lk   = lane & 3;                  // 0..3

    float acc[2][4][4];
    #pragma unroll
    for (int i = 0; i < 2; i++)
        #pragma unroll
        for (int j = 0; j < 4; j++)
            #pragma unroll
            for (int k = 0; k < 4; k++) acc[i][j][k] = 0.f;

    const float* xb = x + (size_t)b * NC * PLANE;

    for (int ci = 0; ci < NCH; ci++) {
        // --- stage weights: raw uint4 copy of pre-packed image ---
        {
            const uint4* src = (const uint4*)(g_Wh + ((size_t)b * NCH + ci) * WS_WORDS);
            uint4* dst = (uint4*)sw;
            #pragma unroll
            for (int j = 0; j < 6; j++) {
                const int idx = tid + j * 320;
                if (idx < WS_WORDS / 4) dst[idx] = src[idx];
            }
        }
        // --- stage x: 16 channels x 3 rows x 162 cols as half2 words ---
        const float* xc = xb + (size_t)ci * 16 * PLANE;
        for (int e = tid; e < 8 * 3 * 162; e += 320) {
            const int cp  = e / 486;
            const int rem = e - cp * 486;
            const int kh  = rem / 162;
            const int i   = rem - kh * 162;
            const int row = h - 1 + kh;
            const int col = i - 1;
            float v0 = 0.f, v1 = 0.f;
            if ((unsigned)col < NW && (unsigned)row < NH) {
                const float* p = xc + (size_t)(2 * cp) * PLANE + row * NW + col;
                v0 = p[0];
                v1 = p[PLANE];
            }
            const __half2 hv = __floats2half2_rn(v0, v1);
            xs[(kh * 162 + i) * 12 + cp] = *(const uint32_t*)&hv;
        }
        __syncthreads();

        #pragma unroll
        for (int tap = 0; tap < KHW; tap++) {
            const int kh = tap / 3;
            const int kw = tap - kh * 3;

            const uint32_t* wrow = sw + tap * (64 * 12);
            uint32_t bf[4][2];
            #pragma unroll
            for (int nt = 0; nt < 4; nt++) {
                const int n = nw + nt * 8 + lg;
                bf[nt][0] = wrow[n * 12 + lk];
                bf[nt][1] = wrow[n * 12 + lk + 4];
            }
            uint32_t af[2][4];
            #pragma unroll
            for (int mt = 0; mt < 2; mt++) {
                const int r = mw + mt * 16 + lg + kw;       // xs col = pixel + kw
                const uint32_t* xr = xs + (kh * 162 + r) * 12;
                af[mt][0] = xr[lk];
                af[mt][1] = xr[8 * 12 + lk];
                af[mt][2] = xr[lk + 4];
                af[mt][3] = xr[8 * 12 + lk + 4];
            }
            #pragma unroll
            for (int mt = 0; mt < 2; mt++)
                #pragma unroll
                for (int nt = 0; nt < 4; nt++)
                    mma16(acc[mt][nt], af[mt], bf[nt]);
        }
        __syncthreads();
    }

    // --- epilogue: d0:(m,n) d1:(m,n+1) d2:(m+8,n) d3:(m+8,n+1) ---
    #pragma unroll
    for (int mt = 0; mt < 2; mt++) {
        const int m = mw + mt * 16 + lg;
        #pragma unroll
        for (int nt = 0; nt < 4; nt++) {
            const int o = nw + nt * 8 + 2 * lk;
            float* ob = out + ((size_t)b * NO + o) * PLANE + (size_t)h * NW;
            ob[m]             = acc[mt][nt][0];
            ob[PLANE + m]     = acc[mt][nt][1];
            ob[m + 8]         = acc[mt][nt][2];
            ob[PLANE + m + 8] = acc[mt][nt][3];
        }
    }
}

// ---------------------------------------------------------------------------
extern "C" void kernel_launch(void* const* d_in, const int* in_sizes, int n_in,
                              void* d_out, int out_size) {
    const float* x      = (const float*)d_in[0];
    const float* scale  = (const float*)d_in[1];
    const float* rw1    = (const float*)d_in[2];
    const float* rb1    = (const float*)d_in[3];
    const float* rw2    = (const float*)d_in[4];
    const float* rb2    = (const float*)d_in[5];
    const float* fc_w   = (const float*)d_in[6];
    const float* bn_g   = (const float*)d_in[7];
    const float* bn_b   = (const float*)d_in[8];
    const float* bn_m   = (const float*)d_in[9];
    const float* bn_v   = (const float*)d_in[10];
    const float* cfc_w  = (const float*)d_in[11];
    const float* cfc_b  = (const float*)d_in[12];
    const float* ffc_w  = (const float*)d_in[13];
    const float* ffc_b  = (const float*)d_in[14];
    const float* sfc_w  = (const float*)d_in[15];
    const float* sfc_b  = (const float*)d_in[16];
    const float* kfc_w  = (const float*)d_in[17];
    const float* kfc_b  = (const float*)d_in[18];
    const float* weight = (const float*)d_in[19];
    float* out = (float*)d_out;

    cudaFuncSetAttribute(conv_kernel, cudaFuncAttributeMaxDynamicSharedMemorySize,
                         SMEM_BYTES);

    gap_kernel<<<NB * NC, 256>>>(x);
    att_kernel<<<NB, 128>>>(scale, rw1, rb1, rw2, rb2, fc_w,
                            bn_g, bn_b, bn_m, bn_v,
                            cfc_w, cfc_b, ffc_w, ffc_b,
                            sfc_w, sfc_b, kfc_w, kfc_b);
    wprep_kernel<<<NB * NO, 288>>>(weight);
    dim3 grid(NH, NB);
    conv_kernel<<<grid, 320, SMEM_BYTES>>>(x, out);
}

// round 7
// speedup vs baseline: 5.7463x; 1.1465x over previous
#include <cuda_runtime.h>
#include <cuda_fp16.h>
#include <cstdint>
#include <math.h>

// Problem constants
#define NB 16
#define NC 64
#define NO 64
#define NH 160
#define NW 160
#define NK 8
#define NA 16
#define KHW 9
#define PLANE (NH*NW)          // 25600
#define NCH 4                  // channel chunks of 16
#define XS_WORDS_BUF (3*162*12)    // 5832 u32 per buffer
#define WS_WORDS_BUF (KHW*NO*12)   // 6912 u32 per buffer
#define SMEM_BYTES ((2*XS_WORDS_BUF + 2*WS_WORDS_BUF) * 4)   // 101952

// Scratch (device globals; no allocation allowed)
__device__ float    g_rows[NB*NH*NC];          // per-(b,row) channel sums
__device__ float    g_chan[NB*NC];
__device__ float    g_filt[NB*NO];
__device__ float    g_spat[NB*KHW];
__device__ float    g_katt[NB*NK];
__device__ uint32_t g_Wh  [NB*NCH*WS_WORDS_BUF];        // pre-packed half2 B image
__device__ uint32_t g_xh  [(size_t)NB*NH*NW*32];        // x as half2, channel-last

// ---------------------------------------------------------------------------
__device__ __forceinline__ uint32_t smem_u32(const void* p) {
    uint32_t a;
    asm("{ .reg .u64 t; cvta.to.shared.u64 t, %1; cvt.u32.u64 %0, t; }" : "=r"(a) : "l"(p));
    return a;
}
__device__ __forceinline__ void mma16(float* d, const uint32_t* a, const uint32_t* b) {
    asm volatile(
        "mma.sync.aligned.m16n8k16.row.col.f32.f16.f16.f32 "
        "{%0,%1,%2,%3}, {%4,%5,%6,%7}, {%8,%9}, {%0,%1,%2,%3};"
        : "+f"(d[0]), "+f"(d[1]), "+f"(d[2]), "+f"(d[3])
        : "r"(a[0]), "r"(a[1]), "r"(a[2]), "r"(a[3]), "r"(b[0]), "r"(b[1]));
}
__device__ __forceinline__ void ldsm_x4(uint32_t& r0, uint32_t& r1, uint32_t& r2,
                                        uint32_t& r3, uint32_t addr) {
    asm volatile("ldmatrix.sync.aligned.m8n8.x4.shared.b16 {%0,%1,%2,%3}, [%4];"
                 : "=r"(r0), "=r"(r1), "=r"(r2), "=r"(r3) : "r"(addr));
}
__device__ __forceinline__ void cp16(uint32_t dst, const void* src, bool valid) {
    const int sz = valid ? 16 : 0;
    asm volatile("cp.async.cg.shared.global [%0], [%1], 16, %2;"
                 :: "r"(dst), "l"(src), "r"(sz) : "memory");
}

// ---------------------------------------------------------------------------
// 1) xprep: x [b][c][h][w] fp32 -> g_xh [b][h][w][cp] half2 (channel-last),
//    plus deterministic per-(b,row) channel sums into g_rows.
//    Block = (row, b), 256 threads, c processed in groups of 8.
// ---------------------------------------------------------------------------
__global__ __launch_bounds__(256)
void xprep_kernel(const float* __restrict__ x) {
    __shared__ float s[8][164];
    const int row = blockIdx.x;
    const int b   = blockIdx.y;
    const int tid = threadIdx.x;
    const int cc  = tid >> 5;            // 0..7
    const int wb  = (tid & 31) * 5;      // 5 cols per lane

    uint32_t* dstrow = g_xh + (((size_t)b * NH + row) * NW) * 32;

    for (int cg = 0; cg < 8; cg++) {
        // load 8 channels x 160 cols, coalesced; accumulate row sums
        const float* src = x + (((size_t)b * NC + cg * 8 + cc) * NH + row) * NW;
        float sum = 0.f;
        #pragma unroll
        for (int j = 0; j < 5; j++) {
            const float v = src[wb + j];
            s[cc][wb + j] = v;
            sum += v;
        }
        #pragma unroll
        for (int off = 16; off; off >>= 1) sum += __shfl_down_sync(0xffffffffu, sum, off);
        if ((tid & 31) == 0)
            g_rows[((size_t)b * NH + row) * NC + cg * 8 + cc] = sum;
        __syncthreads();

        // pack half2 and write channel-last
        for (int e = tid; e < 640; e += 256) {
            const int px = e >> 2;
            const int w4 = e & 3;
            const __half2 hv = __floats2half2_rn(s[2 * w4][px], s[2 * w4 + 1][px]);
            dstrow[(size_t)px * 32 + cg * 4 + w4] = *(const uint32_t*)&hv;
        }
        __syncthreads();
    }
}

// ---------------------------------------------------------------------------
// 2) Routing MLP + BN + 4 attention heads: one block (128 thr) per batch b
// ---------------------------------------------------------------------------
__global__ void att_kernel(const float* __restrict__ scale,
                           const float* __restrict__ rw1, const float* __restrict__ rb1,
                           const float* __restrict__ rw2, const float* __restrict__ rb2,
                           const float* __restrict__ fc_w,
                           const float* __restrict__ bn_g, const float* __restrict__ bn_b,
                           const float* __restrict__ bn_m, const float* __restrict__ bn_v,
                           const float* __restrict__ cfc_w, const float* __restrict__ cfc_b,
                           const float* __restrict__ ffc_w, const float* __restrict__ ffc_b,
                           const float* __restrict__ sfc_w, const float* __restrict__ sfc_b,
                           const float* __restrict__ kfc_w, const float* __restrict__ kfc_b) {
    const int b = blockIdx.x;
    const int t = threadIdx.x;
    __shared__ float s[66], h1[128], rt[64], v[16], kl[8];

    if (t < 2) s[t] = 1.f / scale[t];
    if (t >= 2 && t < 66) {
        const int c = t - 2;
        float a = 0.f;
        for (int r = 0; r < NH; r++) a += g_rows[((size_t)b * NH + r) * NC + c];
        s[t] = a * (1.f / (float)PLANE);
    }
    __syncthreads();
    {   // layer 1: [128,66]
        float a = rb1[t];
        #pragma unroll 6
        for (int i = 0; i < 66; i++) a += rw1[t * 66 + i] * s[i];
        h1[t] = fmaxf(a, 0.f);
    }
    __syncthreads();
    if (t < 64) {   // layer 2: [64,128]
        float a = rb2[t];
        #pragma unroll 8
        for (int i = 0; i < 128; i++) a += rw2[t * 128 + i] * h1[i];
        rt[t] = fmaxf(a, 0.f);
    }
    __syncthreads();
    if (t < NA) {   // trunk: fc (no bias) + BN(eval) + relu
        float a = 0.f;
        #pragma unroll 8
        for (int i = 0; i < 64; i++) a += fc_w[t * 64 + i] * rt[i];
        a = (a - bn_m[t]) * rsqrtf(bn_v[t] + 1e-5f) * bn_g[t] + bn_b[t];
        v[t] = fmaxf(a, 0.f);
    }
    __syncthreads();
    if (t < 64) {
        float a = cfc_b[t], f = ffc_b[t];
        #pragma unroll
        for (int i = 0; i < NA; i++) { a += cfc_w[t * NA + i] * v[i]; f += ffc_w[t * NA + i] * v[i]; }
        g_chan[b * NC + t] = 1.f / (1.f + expf(-a));
        g_filt[b * NO + t] = 1.f / (1.f + expf(-f));
    }
    if (t < KHW) {
        float a = sfc_b[t];
        #pragma unroll
        for (int i = 0; i < NA; i++) a += sfc_w[t * NA + i] * v[i];
        g_spat[b * KHW + t] = 1.f / (1.f + expf(-a));
    }
    if (t < NK) {
        float a = kfc_b[t];
        #pragma unroll
        for (int i = 0; i < NA; i++) a += kfc_w[t * NA + i] * v[i];
        kl[t] = a;
    }
    __syncthreads();
    if (t == 0) {   // softmax over 8 experts
        float m = kl[0];
        #pragma unroll
        for (int i = 1; i < NK; i++) m = fmaxf(m, kl[i]);
        float e[NK], sum = 0.f;
        #pragma unroll
        for (int i = 0; i < NK; i++) { e[i] = expf(kl[i] - m); sum += e[i]; }
        float inv = 1.f / sum;
        #pragma unroll
        for (int i = 0; i < NK; i++) g_katt[b * NK + i] = e[i] * inv;
    }
}

// ---------------------------------------------------------------------------
// 3) Aggregated+gated weights -> half2-packed padded SMEM image.
//    g_Wh[b][chunk][tap][o][word 0..11]: word w = half2 of chunk channels
//    (2w, 2w+1); words 8..11 pad (never read).
// ---------------------------------------------------------------------------
__global__ void wprep_kernel(const float* __restrict__ weight) {
    const int b = blockIdx.x >> 6;
    const int o = blockIdx.x & 63;
    __shared__ float ka[NK], sp[KHW], ch[NC], fo;
    const int t = threadIdx.x;
    if (t < NK)                 ka[t]      = g_katt[b * NK + t];
    else if (t < NK + KHW)      sp[t - NK] = g_spat[b * KHW + (t - NK)];
    else if (t < NK + KHW + NC) ch[t - NK - KHW] = g_chan[b * NC + (t - NK - KHW)];
    else if (t == NK + KHW + NC) fo = g_filt[b * NO + o];
    __syncthreads();

    const float* wo = weight + (size_t)o * (NC * KHW);
    const int cp  = t / KHW;         // 0..31
    const int khw = t - cp * KHW;    // 0..8
    const int c0  = 2 * cp;
    float a0 = 0.f, a1 = 0.f;
    #pragma unroll
    for (int k = 0; k < NK; k++) {
        const float* wk = wo + (size_t)k * NO * NC * KHW;
        a0 += ka[k] * wk[c0 * KHW + khw];
        a1 += ka[k] * wk[(c0 + 1) * KHW + khw];
    }
    const float g = fo * sp[khw];
    const __half2 hv = __floats2half2_rn(a0 * g * ch[c0], a1 * g * ch[c0 + 1]);
    const int chunk = cp >> 3;
    const int w     = cp & 7;
    g_Wh[((((size_t)b * NCH + chunk) * KHW + khw) * NO + o) * 12 + w] =
        *(const uint32_t*)&hv;
}

// ---------------------------------------------------------------------------
// 4) Conv: fp16 m16n8k16 implicit GEMM, cp.async double-buffered staging,
//    ldmatrix fragments. Block = (row h, batch b): M=160 px, N=64 o, K=576.
//    320 thr = 10 warps = 5 M x 2 N groups; warp tile 32x32.
// ---------------------------------------------------------------------------
__global__ __launch_bounds__(320, 2)
void conv_kernel(float* __restrict__ out) {
    extern __shared__ __align__(16) uint32_t dsm[];
    const uint32_t sbase = smem_u32(dsm);
    // layout: xs[2][5832] then ws[2][6912] (u32 words)

    const int h    = blockIdx.x;
    const int b    = blockIdx.y;
    const int tid  = threadIdx.x;
    const int lane = tid & 31;
    const int warp = tid >> 5;
    const int mw   = (warp % 5) * 32;
    const int nw   = (warp / 5) * 32;
    const int l16  = lane & 15;
    const int lq   = lane >> 4;         // k-half
    const int lg   = lane >> 2;
    const int lk   = lane & 3;

    // zero the padded boundary columns (xs cols 0 and 161, words 0..7)
    if (tid < 96) {
        const int w    = tid & 7;
        const int rest = tid >> 3;           // 0..11
        const int col2 = rest & 1;
        const int kh   = (rest >> 1) % 3;
        const int buf  = rest / 6;
        dsm[buf * XS_WORDS_BUF + (kh * 162 + col2 * 161) * 12 + w] = 0u;
    }

    float acc[2][4][4];
    #pragma unroll
    for (int i = 0; i < 2; i++)
        #pragma unroll
        for (int j = 0; j < 4; j++)
            #pragma unroll
            for (int k = 0; k < 4; k++) acc[i][j][k] = 0.f;

    // ---- async stage chunk ci into buffer buf ----
    auto issue_chunk = [&](int ci, int buf) {
        // x: 3 rows x 160 cols x 2x16B
        #pragma unroll
        for (int it = 0; it < 3; it++) {
            const int e   = tid + it * 320;      // < 960
            const int q   = e & 1;
            const int c   = (e >> 1) % 160;
            const int kh  = e / 320;
            const int row = h - 1 + kh;
            const bool valid = (unsigned)row < NH;
            const uint32_t* src = g_xh + (((size_t)b * NH + (valid ? row : 0)) * NW + c) * 32
                                + ci * 8 + q * 4;
            const uint32_t dst = sbase + (buf * XS_WORDS_BUF + (kh * 162 + c + 1) * 12 + q * 4) * 4;
            cp16(dst, src, valid);
        }
        // weights: 6912 words = 1728 x 16B (raw copy of pre-packed image)
        const uint32_t* wsrc = g_Wh + ((size_t)b * NCH + ci) * WS_WORDS_BUF;
        #pragma unroll
        for (int it = 0; it < 6; it++) {
            const int e = tid + it * 320;
            if (e < 1728) {
                const uint32_t dst = sbase + (2 * XS_WORDS_BUF + buf * WS_WORDS_BUF + e * 4) * 4;
                cp16(dst, wsrc + e * 4, true);
            }
        }
        asm volatile("cp.async.commit_group;" ::: "memory");
    };

    issue_chunk(0, 0);

    for (int ci = 0; ci < NCH; ci++) {
        if (ci + 1 < NCH) {
            issue_chunk(ci + 1, (ci + 1) & 1);
            asm volatile("cp.async.wait_group 1;" ::: "memory");
        } else {
            asm volatile("cp.async.wait_group 0;" ::: "memory");
        }
        __syncthreads();

        const int buf = ci & 1;
        const uint32_t xsb = sbase + buf * XS_WORDS_BUF * 4;
        const uint32_t wsb = sbase + (2 * XS_WORDS_BUF + buf * WS_WORDS_BUF) * 4;

        #pragma unroll
        for (int tap = 0; tap < KHW; tap++) {
            const int kh = tap / 3;
            const int kw = tap - kh * 3;

            uint32_t af[2][4], bf[4][2];
            // A fragments: pixel rows, stride 12 words, khalf at +16B
            const uint32_t a0 = xsb + ((kh * 162 + mw + l16 + kw) * 12 + lq * 4) * 4;
            ldsm_x4(af[0][0], af[0][1], af[0][2], af[0][3], a0);
            ldsm_x4(af[1][0], af[1][1], af[1][2], af[1][3], a0 + 16 * 12 * 4);
            // B fragments: n rows, two pairs of 16
            const uint32_t b0 = wsb + tap * (64 * 12 * 4) + ((nw + l16) * 12 + lq * 4) * 4;
            uint32_t r0, r1, r2, r3;
            ldsm_x4(r0, r1, r2, r3, b0);
            bf[0][0] = r0; bf[1][0] = r1; bf[0][1] = r2; bf[1][1] = r3;
            ldsm_x4(r0, r1, r2, r3, b0 + 16 * 12 * 4);
            bf[2][0] = r0; bf[3][0] = r1; bf[2][1] = r2; bf[3][1] = r3;

            #pragma unroll
            for (int mt = 0; mt < 2; mt++)
                #pragma unroll
                for (int nt = 0; nt < 4; nt++)
                    mma16(acc[mt][nt], af[mt], bf[nt]);
        }
        __syncthreads();
    }

    // --- epilogue: d0:(m,n) d1:(m,n+1) d2:(m+8,n) d3:(m+8,n+1) ---
    #pragma unroll
    for (int mt = 0; mt < 2; mt++) {
        const int m = mw + mt * 16 + lg;
        #pragma unroll
        for (int nt = 0; nt < 4; nt++) {
            const int o = nw + nt * 8 + 2 * lk;
            float* ob = out + ((size_t)b * NO + o) * PLANE + (size_t)h * NW;
            ob[m]             = acc[mt][nt][0];
            ob[PLANE + m]     = acc[mt][nt][1];
            ob[m + 8]         = acc[mt][nt][2];
            ob[PLANE + m + 8] = acc[mt][nt][3];
        }
    }
}

// ---------------------------------------------------------------------------
extern "C" void kernel_launch(void* const* d_in, const int* in_sizes, int n_in,
                              void* d_out, int out_size) {
    const float* x      = (const float*)d_in[0];
    const float* scale  = (const float*)d_in[1];
    const float* rw1    = (const float*)d_in[2];
    const float* rb1    = (const float*)d_in[3];
    const float* rw2    = (const float*)d_in[4];
    const float* rb2    = (const float*)d_in[5];
    const float* fc_w   = (const float*)d_in[6];
    const float* bn_g   = (const float*)d_in[7];
    const float* bn_b   = (const float*)d_in[8];
    const float* bn_m   = (const float*)d_in[9];
    const float* bn_v   = (const float*)d_in[10];
    const float* cfc_w  = (const float*)d_in[11];
    const float* cfc_b  = (const float*)d_in[12];
    const float* ffc_w  = (const float*)d_in[13];
    const float* ffc_b  = (const float*)d_in[14];
    const float* sfc_w  = (const float*)d_in[15];
    const float* sfc_b  = (const float*)d_in[16];
    const float* kfc_w  = (const float*)d_in[17];
    const float* kfc_b  = (const float*)d_in[18];
    const float* weight = (const float*)d_in[19];
    float* out = (float*)d_out;

    cudaFuncSetAttribute(conv_kernel, cudaFuncAttributeMaxDynamicSharedMemorySize,
                         SMEM_BYTES);

    dim3 pgrid(NH, NB);
    xprep_kernel<<<pgrid, 256>>>(x);
    att_kernel<<<NB, 128>>>(scale, rw1, rb1, rw2, rb2, fc_w,
                            bn_g, bn_b, bn_m, bn_v,
                            cfc_w, cfc_b, ffc_w, ffc_b,
                            sfc_w, sfc_b, kfc_w, kfc_b);
    wprep_kernel<<<NB * NO, 288>>>(weight);
    dim3 grid(NH, NB);
    conv_kernel<<<grid, 320, SMEM_BYTES>>>(out);
}